// round 13
// baseline (speedup 1.0000x reference)
#include <cuda_runtime.h>

// Involution2d: B=8, C=256, G=4, Cpg=64, K=7, H=W=64, pad=3
// out[b,c,ho,wo] = sum_{kh,kw} in[b,c,ho+kh-3,wo+kw-3] * w[b,g,kh,kw,ho,wo] + bias[c]
//
// R12 vs R11 (35.3us): same TH=4 / 255-reg design point, buy latency slack
//  - loader offsets recomputed inside issue() -> ~12 regs freed for ptxas
//  - explicit row prefetch: row r+1 loads issued before row r FMAs
//  - STAGE_CH 2->4, NBUF 4->3 (wait_group 1): 8 barriers instead of 16

#define TILE_W 32
#define TILE_H 8
#define TH 4
#define SH 14                    // TILE_H + 6
#define SWP 40                   // smem row stride (floats) = loaded window width
#define PLANE (SH*SWP)           // 560 floats
#define WCHUNK 10                // 16B chunks per row
#define SLOTS (SH*WCHUNK)        // 140
#define STAGE_CH 4
#define CH_PER_CTA 32
#define NSTAGES (CH_PER_CTA/STAGE_CH)   // 8
#define NBUF 3
#define CH_B (PLANE*4)           // 2240 B per channel plane
#define BUF_B (STAGE_CH*CH_B)    // 8960 B per buffer
#define NTHR 64
#define NSLOT 3                  // ceil(140/64)

__device__ __forceinline__ void cpa16(unsigned dst, const float* src) {
    asm volatile("cp.async.cg.shared.global [%0], [%1], 16;\n" :: "r"(dst), "l"(src));
}
__device__ __forceinline__ void cpa_commit() {
    asm volatile("cp.async.commit_group;\n" ::: "memory");
}
__device__ __forceinline__ void cpa_wait1() {
    asm volatile("cp.async.wait_group 1;\n" ::: "memory");
}
__device__ __forceinline__ unsigned long long pack2(float a, float b) {
    unsigned long long r;
    asm("mov.b64 %0, {%1, %2};" : "=l"(r) : "f"(a), "f"(b));
    return r;
}
__device__ __forceinline__ void fma2(unsigned long long& d,
                                     unsigned long long a, unsigned long long b) {
    asm("fma.rn.f32x2 %0, %1, %2, %0;" : "+l"(d) : "l"(a), "l"(b));
}
__device__ __forceinline__ float hadd2(unsigned long long v) {
    float lo, hi;
    asm("mov.b64 {%0, %1}, %2;" : "=f"(lo), "=f"(hi) : "l"(v));
    return lo + hi;
}

__global__ __launch_bounds__(NTHR, 4)
void involution2d_kernel(const float* __restrict__ input,
                         const float* __restrict__ weight,
                         const float* __restrict__ bias,
                         float* __restrict__ out)
{
    __shared__ __align__(16) float tile[NBUF * STAGE_CH * PLANE];
    __shared__ float sbias[CH_PER_CTA];

    const int tx  = threadIdx.x;            // 0..31
    const int ty  = threadIdx.y;            // 0..1
    const int tid = ty * 32 + tx;           // 0..63

    int bid = blockIdx.x;
    const int half = bid & 1; bid >>= 1;    // channel half
    const int wt = bid & 1;  bid >>= 1;     // 2 tiles across W
    const int ht = bid & 7;  bid >>= 3;     // 8 tiles across H
    const int g  = bid & 3;  bid >>= 2;     // 4 groups
    const int b  = bid;                     // 8 batches

    const int ch0 = half * CH_PER_CTA;
    const int w0g = wt * TILE_W;
    const int h0g = ht * TILE_H;
    const int oy0 = ty * TH;                // 0 or 4
    const int ho0 = h0g + oy0;
    const int wo  = w0g + tx;

    if (tid < CH_PER_CTA) sbias[tid] = bias[g * 64 + ch0 + tid];

    // ---- compute-side window offsets (window base = w0g-4; tap j -> idx tx+1+j) ----
    const int base  = tx + 1;
    const int p     = base & 1;
    const int jp0   = p;                     // first paired tap
    const int jscal = p ? 0 : 6;             // scalar tap
    const int pairIdx = base + p;            // even -> 8B aligned
    const int scalIdx = base + jscal;

    // ---- weights: 4 rows x 49 = 196 regs/thread, parity pairing, read once ----
    unsigned long long wp[TH][7][3];
    float ws[TH][7];
    {
        const float* wb = weight + ((size_t)(b * 4 + g) * 49) * 4096 + ho0 * 64 + wo;
        #pragma unroll
        for (int t = 0; t < TH; ++t) {
            const float* wt_ = wb + t * 64;
            #pragma unroll
            for (int r = 0; r < 7; ++r) {
                #pragma unroll
                for (int m = 0; m < 3; ++m) {
                    int k = r * 7 + jp0 + 2 * m;
                    wp[t][r][m] = pack2(wt_[k * 4096], wt_[(k + 1) * 4096]);
                }
                ws[t][r] = wt_[(r * 7 + jscal) * 4096];
            }
        }
    }

    const float* inb  = input + (b * 256 + g * 64 + ch0) * 4096;
    float*       outb = out   + (b * 256 + g * 64 + ch0) * 4096;
    const unsigned sbase = (unsigned)__cvta_generic_to_shared(&tile[0]);

    // ---- one-time halo zero fill (constant across channels, all planes) ----
    #pragma unroll
    for (int q = 0; q < NSLOT; ++q) {
        int slot = tid + q * NTHR;
        if (slot < SLOTS) {
            int row = slot / WCHUNK;
            int ck  = slot - row * WCHUNK;
            int gh  = h0g - 3 + row;
            int gw  = w0g - 4 + 4 * ck;
            bool ok = ((unsigned)gh < 64u) && ((unsigned)gw < 64u);
            if (!ok) {
                float* z = &tile[(row * SWP + 4 * ck)];
                #pragma unroll
                for (int pl = 0; pl < NBUF * STAGE_CH; ++pl) {
                    float4* z4 = (float4*)(z + pl * PLANE);
                    *z4 = make_float4(0.f, 0.f, 0.f, 0.f);
                }
            }
        }
    }

    // ---- issue one 4-channel stage; offsets recomputed (no live regs held) ----
    auto issue = [&](int stage, int bi) {
        const float* gsrc = inb + (size_t)stage * (STAGE_CH * 4096);
        const unsigned bA = sbase + (unsigned)bi * BUF_B;
        #pragma unroll
        for (int q = 0; q < NSLOT; ++q) {
            int slot = tid + q * NTHR;
            if (slot < SLOTS) {
                int row = slot / WCHUNK;
                int ck  = slot - row * WCHUNK;
                int gh  = h0g - 3 + row;
                int gw  = w0g - 4 + 4 * ck;
                if (((unsigned)gh < 64u) && ((unsigned)gw < 64u)) {
                    int go = gh * 64 + gw;
                    unsigned so = (unsigned)(row * SWP + 4 * ck) * 4u;
                    #pragma unroll
                    for (int c = 0; c < STAGE_CH; ++c)
                        cpa16(bA + (unsigned)c * CH_B + so, gsrc + c * 4096 + go);
                }
            }
        }
    };

    // ---- prologue: stages 0,1 into buffers 0,1 ----
    issue(0, 0); cpa_commit();
    issue(1, 1); cpa_commit();

    int cb = 0;            // buffer holding stage s
    int ib = 2;            // buffer for stage s+2
    for (int s = 0; s < NSTAGES; ++s) {
        cpa_wait1();                 // stage s landed (<=1 group pending)
        __syncthreads();             // buffer ib free; stage s visible (2 warps)

        if (s + 2 < NSTAGES) issue(s + 2, ib);
        cpa_commit();                // empty tail groups harmless

        // ---- compute the 4 channels of stage s, 4 output rows each ----
        const float* bufp = &tile[cb * STAGE_CH * PLANE];
        #pragma unroll
        for (int c = 0; c < STAGE_CH; ++c) {
            const float* plane = bufp + c * PLANE + oy0 * SWP;
            const float bv = sbias[s * STAGE_CH + c];
            unsigned long long acc[TH];
            float accs[TH];
            #pragma unroll
            for (int t = 0; t < TH; ++t) { acc[t] = 0ull; accs[t] = bv; }

            // software-pipelined rows: load r+1 before FMAs of r
            unsigned long long p0, p1, p2, n0, n1, n2;
            float xs, xn;
            {
                const float* rowf = plane;
                const unsigned long long* rp =
                    (const unsigned long long*)(rowf + pairIdx);
                p0 = rp[0]; p1 = rp[1]; p2 = rp[2]; xs = rowf[scalIdx];
            }
            #pragma unroll
            for (int r = 0; r < TH + 6; ++r) {       // 10 input rows
                if (r < TH + 5) {
                    const float* rowf = plane + (r + 1) * SWP;
                    const unsigned long long* rp =
                        (const unsigned long long*)(rowf + pairIdx);
                    n0 = rp[0]; n1 = rp[1]; n2 = rp[2]; xn = rowf[scalIdx];
                }
                #pragma unroll
                for (int t = 0; t < TH; ++t) {
                    if (r >= t && r <= t + 6) {      // compile-time per (r,t)
                        const int kr = r - t;
                        fma2(acc[t], p0, wp[t][kr][0]);
                        fma2(acc[t], p1, wp[t][kr][1]);
                        fma2(acc[t], p2, wp[t][kr][2]);
                        accs[t] = fmaf(xs, ws[t][kr], accs[t]);
                    }
                }
                p0 = n0; p1 = n1; p2 = n2; xs = xn;
            }
            const int ch = s * STAGE_CH + c;
            float* op = outb + ch * 4096 + ho0 * 64 + wo;
            #pragma unroll
            for (int t = 0; t < TH; ++t)
                op[t * 64] = hadd2(acc[t]) + accs[t];
        }

        cb = (cb == NBUF - 1) ? 0 : cb + 1;
        ib = (ib == NBUF - 1) ? 0 : ib + 1;
    }
}

extern "C" void kernel_launch(void* const* d_in, const int* in_sizes, int n_in,
                              void* d_out, int out_size)
{
    const float* input  = (const float*)d_in[0];
    const float* weight = (const float*)d_in[1];
    const float* bias   = (const float*)d_in[2];
    float*       out    = (float*)d_out;

    dim3 block(TILE_W, 2, 1);                 // 64 threads
    dim3 grid(8 * 4 * 8 * 2 * 2, 1, 1);       // B*G*Ht*Wt*chhalves = 1024
    involution2d_kernel<<<grid, block>>>(input, weight, bias, out);
}

// round 14
// speedup vs baseline: 1.0098x; 1.0098x over previous
#include <cuda_runtime.h>

// Involution2d: B=8, C=256, G=4, Cpg=64, K=7, H=W=64, pad=3
// out[b,c,ho,wo] = sum_{kh,kw} in[b,c,ho+kh-3,wo+kw-3] * w[b,g,kh,kw,ho,wo] + bias[c]
//
// R13 = R11 (35.3us, best) + ONLY the register-neutral/negative changes from R12:
//  - loader offsets recomputed inside issue() -> ~12 regs freed (scheduling headroom
//    so ptxas can hoist next-row LDS itself; manual prefetch in R12 cost regs = bad)
//  - STAGE_CH 2->4, NBUF 4->3 (wait_group 1): 8 barriers/CTA instead of 16
//  - NO manual row prefetch, NO chain split (both regressed at the 255-reg cap)

#define TILE_W 32
#define TILE_H 8
#define TH 4
#define SH 14                    // TILE_H + 6
#define SWP 40                   // smem row stride (floats) = loaded window width
#define PLANE (SH*SWP)           // 560 floats
#define WCHUNK 10                // 16B chunks per row
#define SLOTS (SH*WCHUNK)        // 140
#define STAGE_CH 4
#define CH_PER_CTA 32
#define NSTAGES (CH_PER_CTA/STAGE_CH)   // 8
#define NBUF 3
#define CH_B (PLANE*4)           // 2240 B per channel plane
#define BUF_B (STAGE_CH*CH_B)    // 8960 B per buffer
#define NTHR 64
#define NSLOT 3                  // ceil(140/64)

__device__ __forceinline__ void cpa16(unsigned dst, const float* src) {
    asm volatile("cp.async.cg.shared.global [%0], [%1], 16;\n" :: "r"(dst), "l"(src));
}
__device__ __forceinline__ void cpa_commit() {
    asm volatile("cp.async.commit_group;\n" ::: "memory");
}
__device__ __forceinline__ void cpa_wait1() {
    asm volatile("cp.async.wait_group 1;\n" ::: "memory");
}
__device__ __forceinline__ unsigned long long pack2(float a, float b) {
    unsigned long long r;
    asm("mov.b64 %0, {%1, %2};" : "=l"(r) : "f"(a), "f"(b));
    return r;
}
__device__ __forceinline__ void fma2(unsigned long long& d,
                                     unsigned long long a, unsigned long long b) {
    asm("fma.rn.f32x2 %0, %1, %2, %0;" : "+l"(d) : "l"(a), "l"(b));
}
__device__ __forceinline__ float hadd2(unsigned long long v) {
    float lo, hi;
    asm("mov.b64 {%0, %1}, %2;" : "=f"(lo), "=f"(hi) : "l"(v));
    return lo + hi;
}

__global__ __launch_bounds__(NTHR, 4)
void involution2d_kernel(const float* __restrict__ input,
                         const float* __restrict__ weight,
                         const float* __restrict__ bias,
                         float* __restrict__ out)
{
    __shared__ __align__(16) float tile[NBUF * STAGE_CH * PLANE];
    __shared__ float sbias[CH_PER_CTA];

    const int tx  = threadIdx.x;            // 0..31
    const int ty  = threadIdx.y;            // 0..1
    const int tid = ty * 32 + tx;           // 0..63

    int bid = blockIdx.x;
    const int half = bid & 1; bid >>= 1;    // channel half
    const int wt = bid & 1;  bid >>= 1;     // 2 tiles across W
    const int ht = bid & 7;  bid >>= 3;     // 8 tiles across H
    const int g  = bid & 3;  bid >>= 2;     // 4 groups
    const int b  = bid;                     // 8 batches

    const int ch0 = half * CH_PER_CTA;
    const int w0g = wt * TILE_W;
    const int h0g = ht * TILE_H;
    const int oy0 = ty * TH;                // 0 or 4
    const int ho0 = h0g + oy0;
    const int wo  = w0g + tx;

    if (tid < CH_PER_CTA) sbias[tid] = bias[g * 64 + ch0 + tid];

    // ---- compute-side window offsets (window base = w0g-4; tap j -> idx tx+1+j) ----
    const int base  = tx + 1;
    const int p     = base & 1;
    const int jp0   = p;                     // first paired tap
    const int jscal = p ? 0 : 6;             // scalar tap
    const int pairIdx = base + p;            // even -> 8B aligned
    const int scalIdx = base + jscal;

    // ---- weights: 4 rows x 49 = 196 regs/thread, parity pairing, read once ----
    unsigned long long wp[TH][7][3];
    float ws[TH][7];
    {
        const float* wb = weight + ((size_t)(b * 4 + g) * 49) * 4096 + ho0 * 64 + wo;
        #pragma unroll
        for (int t = 0; t < TH; ++t) {
            const float* wt_ = wb + t * 64;
            #pragma unroll
            for (int r = 0; r < 7; ++r) {
                #pragma unroll
                for (int m = 0; m < 3; ++m) {
                    int k = r * 7 + jp0 + 2 * m;
                    wp[t][r][m] = pack2(wt_[k * 4096], wt_[(k + 1) * 4096]);
                }
                ws[t][r] = wt_[(r * 7 + jscal) * 4096];
            }
        }
    }

    const float* inb  = input + (b * 256 + g * 64 + ch0) * 4096;
    float*       outb = out   + (b * 256 + g * 64 + ch0) * 4096;
    const unsigned sbase = (unsigned)__cvta_generic_to_shared(&tile[0]);

    // ---- one-time halo zero fill (constant across channels, all planes) ----
    #pragma unroll
    for (int q = 0; q < NSLOT; ++q) {
        int slot = tid + q * NTHR;
        if (slot < SLOTS) {
            int row = slot / WCHUNK;
            int ck  = slot - row * WCHUNK;
            int gh  = h0g - 3 + row;
            int gw  = w0g - 4 + 4 * ck;
            bool ok = ((unsigned)gh < 64u) && ((unsigned)gw < 64u);
            if (!ok) {
                float* z = &tile[(row * SWP + 4 * ck)];
                #pragma unroll
                for (int pl = 0; pl < NBUF * STAGE_CH; ++pl) {
                    float4* z4 = (float4*)(z + pl * PLANE);
                    *z4 = make_float4(0.f, 0.f, 0.f, 0.f);
                }
            }
        }
    }

    // ---- issue one 4-channel stage; offsets recomputed (no live regs held) ----
    auto issue = [&](int stage, int bi) {
        const float* gsrc = inb + (size_t)stage * (STAGE_CH * 4096);
        const unsigned bA = sbase + (unsigned)bi * BUF_B;
        #pragma unroll
        for (int q = 0; q < NSLOT; ++q) {
            int slot = tid + q * NTHR;
            if (slot < SLOTS) {
                int row = slot / WCHUNK;
                int ck  = slot - row * WCHUNK;
                int gh  = h0g - 3 + row;
                int gw  = w0g - 4 + 4 * ck;
                if (((unsigned)gh < 64u) && ((unsigned)gw < 64u)) {
                    int go = gh * 64 + gw;
                    unsigned so = (unsigned)(row * SWP + 4 * ck) * 4u;
                    #pragma unroll
                    for (int c = 0; c < STAGE_CH; ++c)
                        cpa16(bA + (unsigned)c * CH_B + so, gsrc + c * 4096 + go);
                }
            }
        }
    };

    // ---- prologue: stages 0,1 into buffers 0,1 ----
    issue(0, 0); cpa_commit();
    issue(1, 1); cpa_commit();

    int cb = 0;            // buffer holding stage s
    int ib = 2;            // buffer for stage s+2
    for (int s = 0; s < NSTAGES; ++s) {
        cpa_wait1();                 // stage s landed (<=1 group pending)
        __syncthreads();             // buffer ib free; stage s visible (2 warps)

        if (s + 2 < NSTAGES) issue(s + 2, ib);
        cpa_commit();                // empty tail groups harmless

        // ---- compute the 4 channels of stage s, 4 output rows each ----
        const float* bufp = &tile[cb * STAGE_CH * PLANE];
        #pragma unroll
        for (int c = 0; c < STAGE_CH; ++c) {
            const float* plane = bufp + c * PLANE + oy0 * SWP;
            const float bv = sbias[s * STAGE_CH + c];
            unsigned long long acc[TH];
            float accs[TH];
            #pragma unroll
            for (int t = 0; t < TH; ++t) { acc[t] = 0ull; accs[t] = bv; }

            #pragma unroll
            for (int r = 0; r < TH + 6; ++r) {       // 10 input rows
                const float* rowf = plane + r * SWP;
                const unsigned long long* rp =
                    (const unsigned long long*)(rowf + pairIdx);
                unsigned long long p0 = rp[0], p1 = rp[1], p2 = rp[2];
                float xs = rowf[scalIdx];
                #pragma unroll
                for (int t = 0; t < TH; ++t) {
                    if (r >= t && r <= t + 6) {      // compile-time per (r,t)
                        const int kr = r - t;
                        fma2(acc[t], p0, wp[t][kr][0]);
                        fma2(acc[t], p1, wp[t][kr][1]);
                        fma2(acc[t], p2, wp[t][kr][2]);
                        accs[t] = fmaf(xs, ws[t][kr], accs[t]);
                    }
                }
            }
            const int ch = s * STAGE_CH + c;
            float* op = outb + ch * 4096 + ho0 * 64 + wo;
            #pragma unroll
            for (int t = 0; t < TH; ++t)
                op[t * 64] = hadd2(acc[t]) + accs[t];
        }

        cb = (cb == NBUF - 1) ? 0 : cb + 1;
        ib = (ib == NBUF - 1) ? 0 : ib + 1;
    }
}

extern "C" void kernel_launch(void* const* d_in, const int* in_sizes, int n_in,
                              void* d_out, int out_size)
{
    const float* input  = (const float*)d_in[0];
    const float* weight = (const float*)d_in[1];
    const float* bias   = (const float*)d_in[2];
    float*       out    = (float*)d_out;

    dim3 block(TILE_W, 2, 1);                 // 64 threads
    dim3 grid(8 * 4 * 8 * 2 * 2, 1, 1);       // B*G*Ht*Wt*chhalves = 1024
    involution2d_kernel<<<grid, block>>>(input, weight, bias, out);
}

// round 15
// speedup vs baseline: 1.0672x; 1.0568x over previous
#include <cuda_runtime.h>

// Involution2d: B=8, C=256, G=4, Cpg=64, K=7, H=W=64, pad=3
// out[b,c,ho,wo] = sum_{kh,kw} in[b,c,ho+kh-3,wo+kw-3] * w[b,g,kh,kw,ho,wo] + bias[c]
//
// R14 = exact R11 (35.3us best) + ONE isolated change:
//  - loader offsets recomputed inside issue() (9 live regs freed from main loop)
//  - STAGE_CH=2, NBUF=4, wait_group 2 KEPT (R12/R13 proved STAGE_CH=4 regresses)

#define TILE_W 32
#define TILE_H 8
#define TH 4
#define SH 14                    // TILE_H + 6
#define SWP 40                   // smem row stride (floats) = loaded window width
#define PLANE (SH*SWP)           // 560 floats
#define WCHUNK 10                // 16B chunks per row
#define SLOTS (SH*WCHUNK)        // 140
#define STAGE_CH 2
#define CH_PER_CTA 32
#define NSTAGES (CH_PER_CTA/STAGE_CH)   // 16
#define NBUF 4
#define CH_B (PLANE*4)           // 2240 B per channel plane
#define BUF_B (STAGE_CH*CH_B)    // 4480 B per buffer
#define NTHR 64
#define NSLOT 3                  // ceil(140/64)

__device__ __forceinline__ void cpa16(unsigned dst, const float* src) {
    asm volatile("cp.async.cg.shared.global [%0], [%1], 16;\n" :: "r"(dst), "l"(src));
}
__device__ __forceinline__ void cpa_commit() {
    asm volatile("cp.async.commit_group;\n" ::: "memory");
}
__device__ __forceinline__ void cpa_wait2() {
    asm volatile("cp.async.wait_group 2;\n" ::: "memory");
}
__device__ __forceinline__ unsigned long long pack2(float a, float b) {
    unsigned long long r;
    asm("mov.b64 %0, {%1, %2};" : "=l"(r) : "f"(a), "f"(b));
    return r;
}
__device__ __forceinline__ void fma2(unsigned long long& d,
                                     unsigned long long a, unsigned long long b) {
    asm("fma.rn.f32x2 %0, %1, %2, %0;" : "+l"(d) : "l"(a), "l"(b));
}
__device__ __forceinline__ float hadd2(unsigned long long v) {
    float lo, hi;
    asm("mov.b64 {%0, %1}, %2;" : "=f"(lo), "=f"(hi) : "l"(v));
    return lo + hi;
}

__global__ __launch_bounds__(NTHR, 4)
void involution2d_kernel(const float* __restrict__ input,
                         const float* __restrict__ weight,
                         const float* __restrict__ bias,
                         float* __restrict__ out)
{
    __shared__ __align__(16) float tile[NBUF * STAGE_CH * PLANE];
    __shared__ float sbias[CH_PER_CTA];

    const int tx  = threadIdx.x;            // 0..31
    const int ty  = threadIdx.y;            // 0..1
    const int tid = ty * 32 + tx;           // 0..63

    int bid = blockIdx.x;
    const int half = bid & 1; bid >>= 1;    // channel half
    const int wt = bid & 1;  bid >>= 1;     // 2 tiles across W
    const int ht = bid & 7;  bid >>= 3;     // 8 tiles across H
    const int g  = bid & 3;  bid >>= 2;     // 4 groups
    const int b  = bid;                     // 8 batches

    const int ch0 = half * CH_PER_CTA;
    const int w0g = wt * TILE_W;
    const int h0g = ht * TILE_H;
    const int oy0 = ty * TH;                // 0 or 4
    const int ho0 = h0g + oy0;
    const int wo  = w0g + tx;

    if (tid < CH_PER_CTA) sbias[tid] = bias[g * 64 + ch0 + tid];

    // ---- compute-side window offsets (window base = w0g-4; tap j -> idx tx+1+j) ----
    const int base  = tx + 1;
    const int p     = base & 1;
    const int jp0   = p;                     // first paired tap
    const int jscal = p ? 0 : 6;             // scalar tap
    const int pairIdx = base + p;            // even -> 8B aligned
    const int scalIdx = base + jscal;

    // ---- weights: 4 rows x 49 = 196 regs/thread, parity pairing, read once ----
    unsigned long long wp[TH][7][3];
    float ws[TH][7];
    {
        const float* wb = weight + ((size_t)(b * 4 + g) * 49) * 4096 + ho0 * 64 + wo;
        #pragma unroll
        for (int t = 0; t < TH; ++t) {
            const float* wt_ = wb + t * 64;
            #pragma unroll
            for (int r = 0; r < 7; ++r) {
                #pragma unroll
                for (int m = 0; m < 3; ++m) {
                    int k = r * 7 + jp0 + 2 * m;
                    wp[t][r][m] = pack2(wt_[k * 4096], wt_[(k + 1) * 4096]);
                }
                ws[t][r] = wt_[(r * 7 + jscal) * 4096];
            }
        }
    }

    const float* inb  = input + (b * 256 + g * 64 + ch0) * 4096;
    float*       outb = out   + (b * 256 + g * 64 + ch0) * 4096;
    const unsigned sbase = (unsigned)__cvta_generic_to_shared(&tile[0]);

    // ---- one-time halo zero fill (constant across channels, all planes) ----
    #pragma unroll
    for (int q = 0; q < NSLOT; ++q) {
        int slot = tid + q * NTHR;
        if (slot < SLOTS) {
            int row = slot / WCHUNK;
            int ck  = slot - row * WCHUNK;
            int gh  = h0g - 3 + row;
            int gw  = w0g - 4 + 4 * ck;
            bool ok = ((unsigned)gh < 64u) && ((unsigned)gw < 64u);
            if (!ok) {
                float* z = &tile[(row * SWP + 4 * ck)];
                #pragma unroll
                for (int pl = 0; pl < NBUF * STAGE_CH; ++pl) {
                    float4* z4 = (float4*)(z + pl * PLANE);
                    *z4 = make_float4(0.f, 0.f, 0.f, 0.f);
                }
            }
        }
    }

    // ---- issue one 2-channel stage; offsets recomputed (no live regs held) ----
    auto issue = [&](int stage, int bi) {
        const float* gsrc = inb + (size_t)stage * (STAGE_CH * 4096);
        const unsigned bA = sbase + (unsigned)bi * BUF_B;
        #pragma unroll
        for (int q = 0; q < NSLOT; ++q) {
            int slot = tid + q * NTHR;
            if (slot < SLOTS) {
                int row = slot / WCHUNK;
                int ck  = slot - row * WCHUNK;
                int gh  = h0g - 3 + row;
                int gw  = w0g - 4 + 4 * ck;
                if (((unsigned)gh < 64u) && ((unsigned)gw < 64u)) {
                    int go = gh * 64 + gw;
                    unsigned so = (unsigned)(row * SWP + 4 * ck) * 4u;
                    #pragma unroll
                    for (int c = 0; c < STAGE_CH; ++c)
                        cpa16(bA + (unsigned)c * CH_B + so, gsrc + c * 4096 + go);
                }
            }
        }
    };

    // ---- prologue: stages 0..2 into buffers 0..2 ----
    issue(0, 0); cpa_commit();
    issue(1, 1); cpa_commit();
    issue(2, 2); cpa_commit();

    int cb = 0;            // buffer holding stage s
    int ib = 3;            // buffer for stage s+3
    for (int s = 0; s < NSTAGES; ++s) {
        cpa_wait2();                 // stage s landed (<=2 groups pending)
        __syncthreads();             // buffer ib free; stage s visible (2 warps)

        if (s + 3 < NSTAGES) issue(s + 3, ib);
        cpa_commit();                // empty tail groups harmless

        // ---- compute the 2 channels of stage s, 4 output rows each ----
        const float* bufp = &tile[cb * STAGE_CH * PLANE];
        #pragma unroll
        for (int c = 0; c < STAGE_CH; ++c) {
            const float* plane = bufp + c * PLANE + oy0 * SWP;
            const float bv = sbias[s * STAGE_CH + c];
            unsigned long long acc[TH];
            float accs[TH];
            #pragma unroll
            for (int t = 0; t < TH; ++t) { acc[t] = 0ull; accs[t] = bv; }

            #pragma unroll
            for (int r = 0; r < TH + 6; ++r) {       // 10 input rows
                const float* rowf = plane + r * SWP;
                const unsigned long long* rp =
                    (const unsigned long long*)(rowf + pairIdx);
                unsigned long long p0 = rp[0], p1 = rp[1], p2 = rp[2];
                float xs = rowf[scalIdx];
                #pragma unroll
                for (int t = 0; t < TH; ++t) {
                    if (r >= t && r <= t + 6) {      // compile-time per (r,t)
                        const int kr = r - t;
                        fma2(acc[t], p0, wp[t][kr][0]);
                        fma2(acc[t], p1, wp[t][kr][1]);
                        fma2(acc[t], p2, wp[t][kr][2]);
                        accs[t] = fmaf(xs, ws[t][kr], accs[t]);
                    }
                }
            }
            const int ch = s * STAGE_CH + c;
            float* op = outb + ch * 4096 + ho0 * 64 + wo;
            #pragma unroll
            for (int t = 0; t < TH; ++t)
                op[t * 64] = hadd2(acc[t]) + accs[t];
        }

        cb = (cb == NBUF - 1) ? 0 : cb + 1;
        ib = (ib == NBUF - 1) ? 0 : ib + 1;
    }
}

extern "C" void kernel_launch(void* const* d_in, const int* in_sizes, int n_in,
                              void* d_out, int out_size)
{
    const float* input  = (const float*)d_in[0];
    const float* weight = (const float*)d_in[1];
    const float* bias   = (const float*)d_in[2];
    float*       out    = (float*)d_out;

    dim3 block(TILE_W, 2, 1);                 // 64 threads
    dim3 grid(8 * 4 * 8 * 2 * 2, 1, 1);       // B*G*Ht*Wt*chhalves = 1024
    involution2d_kernel<<<grid, block>>>(input, weight, bias, out);
}